// round 10
// baseline (speedup 1.0000x reference)
#include <cuda_runtime.h>
#include <cstddef>

#define B_  32
#define S_  8192
#define H2_ 256
#define CHUNKS 32
#define SPC (S_ / CHUNKS)      // 256 s-rows per block
#define NBLK (B_ * CHUNKS)     // 1024 blocks
#define PSTRIDE (H2_ + 1)
#define USLICES 8              // d-dimension slices for k_u1

// ---- scratch (allocation-free) ----
__device__ float g_upart[B_ * USLICES * H2_];       // partial u per d-slice
__device__ float g_part[NBLK * PSTRIDE];            // per-block partial acc[256] + Z
__device__ unsigned g_cnt[B_];                      // arrival counters (self-resetting)

// ---------------- k_u1: partial u[b,e] over a 32-wide d-slice ----------------
__global__ void __launch_bounds__(256) k_u1(const float* __restrict__ hd,
                                            const float* __restrict__ W) {
    int blk = blockIdx.x;            // 256 blocks
    int b = blk >> 3;
    int sl = blk & 7;
    int e = threadIdx.x;
    __shared__ float sh[32];
    if (e < 32) sh[e] = hd[b * H2_ + sl * 32 + e];
    __syncthreads();
    const float* Wp = W + (size_t)(sl * 32) * H2_ + e;
    float acc = 0.f;
#pragma unroll
    for (int d = 0; d < 32; d++) acc += sh[d] * Wp[(size_t)d * H2_];
    g_upart[blk * H2_ + e] = acc;
}

// ---------------- k_main: fused scores + accumulation + per-batch epilogue ----------------
__global__ void __launch_bounds__(256) k_main(
    const float* __restrict__ henc,
    const float* __restrict__ mask,
    const float* __restrict__ sums,
    float* __restrict__ alphat_out,
    float* __restrict__ newsum_out,
    float* __restrict__ ct)
{
    int blk = blockIdx.x;
    int b = blk >> 5;            // / CHUNKS
    int chunk = blk & 31;        // % CHUNKS
    int tid = threadIdx.x;
    int w = tid >> 5;
    int l = tid & 31;

    // u[b] reconstructed from 8 L2-resident d-slice partials.
    // lane l holds dims [4l,4l+4) and [128+4l,128+4l+4)
    float4 u0 = make_float4(0.f, 0.f, 0.f, 0.f);
    float4 u1 = make_float4(0.f, 0.f, 0.f, 0.f);
#pragma unroll
    for (int s2 = 0; s2 < USLICES; s2++) {
        const float4* p = reinterpret_cast<const float4*>(
            g_upart + (size_t)(b * USLICES + s2) * H2_);
        float4 t0 = p[l];
        float4 t1 = p[l + 32];
        u0.x += t0.x; u0.y += t0.y; u0.z += t0.z; u0.w += t0.w;
        u1.x += t1.x; u1.y += t1.y; u1.z += t1.z; u1.w += t1.w;
    }

    float acc0x = 0.f, acc0y = 0.f, acc0z = 0.f, acc0w = 0.f;
    float acc1x = 0.f, acc1y = 0.f, acc1z = 0.f, acc1w = 0.f;
    float Z = 0.f;

    int s0 = chunk * SPC;
    const float4* base = reinterpret_cast<const float4*>(
        henc + ((size_t)b * S_ + s0) * H2_);
    const float* sums_b = sums + b * S_ + s0;
    const float* mask_b = mask + b * S_ + s0;
    float* newsum_b = newsum_out + b * S_ + s0;
    float* alphat_b = alphat_out + b * S_ + s0;

    // 2-row unroll per warp: rows i (A) and i+8 (B) -> MLP=4 LDG.128 per warp
    for (int i = w; i < SPC; i += 16) {
        int j = i + 8;
        const float4* rowA = base + (size_t)i * (H2_ / 4);
        const float4* rowB = base + (size_t)j * (H2_ / 4);
        float4 a0 = __ldcs(rowA + l);
        float4 a1 = __ldcs(rowA + l + 32);
        float4 b0 = __ldcs(rowB + l);
        float4 b1 = __ldcs(rowB + l + 32);

        float dA = a0.x * u0.x + a0.y * u0.y + a0.z * u0.z + a0.w * u0.w
                 + a1.x * u1.x + a1.y * u1.y + a1.z * u1.z + a1.w * u1.w;
        float dB = b0.x * u0.x + b0.y * u0.y + b0.z * u0.z + b0.w * u0.w
                 + b1.x * u1.x + b1.y * u1.y + b1.z * u1.z + b1.w * u1.w;
#pragma unroll
        for (int o = 16; o; o >>= 1) {      // two independent shfl chains overlap
            dA += __shfl_xor_sync(0xffffffffu, dA, o);
            dB += __shfl_xor_sync(0xffffffffu, dB, o);
        }

        float seA = 0.f, mA = 0.f, seB = 0.f, mB = 0.f;
        if (l == 0) {
            seA = sums_b[i]; mA = mask_b[i];
            seB = sums_b[j]; mB = mask_b[j];
        }
        seA = __shfl_sync(0xffffffffu, seA, 0);
        mA  = __shfl_sync(0xffffffffu, mA, 0);
        seB = __shfl_sync(0xffffffffu, seB, 0);
        mB  = __shfl_sync(0xffffffffu, mB, 0);

        float eA = __expf(dA);
        float eB = __expf(dB);
        float aA = (eA / seA) * mA;
        float aB = (eB / seB) * mB;
        if (l == 0) {
            newsum_b[i] = seA + eA;
            alphat_b[i] = aA;            // scaled by invZ in epilogue
            newsum_b[j] = seB + eB;
            alphat_b[j] = aB;
        }
        Z += aA + aB;
        acc0x += aA * a0.x + aB * b0.x;
        acc0y += aA * a0.y + aB * b0.y;
        acc0z += aA * a0.z + aB * b0.z;
        acc0w += aA * a0.w + aB * b0.w;
        acc1x += aA * a1.x + aB * b1.x;
        acc1y += aA * a1.y + aB * b1.y;
        acc1z += aA * a1.z + aB * b1.z;
        acc1w += aA * a1.w + aB * b1.w;
    }

    // block-level reduction of acc[256] across 8 warps (deterministic order)
    __shared__ float sacc[8][H2_];
    __shared__ float sZ[8];
    float* my = sacc[w];
    my[4 * l + 0] = acc0x; my[4 * l + 1] = acc0y;
    my[4 * l + 2] = acc0z; my[4 * l + 3] = acc0w;
    my[128 + 4 * l + 0] = acc1x; my[128 + 4 * l + 1] = acc1y;
    my[128 + 4 * l + 2] = acc1z; my[128 + 4 * l + 3] = acc1w;
    if (l == 0) sZ[w] = Z;
    __syncthreads();

    float tot = 0.f;
#pragma unroll
    for (int ww = 0; ww < 8; ww++) tot += sacc[ww][tid];
    g_part[blk * PSTRIDE + tid] = tot;
    if (tid == 0) {
        float z = 0.f;
#pragma unroll
        for (int ww = 0; ww < 8; ww++) z += sZ[ww];
        g_part[blk * PSTRIDE + H2_] = z;
    }

    // ---- last-block-per-batch epilogue (threadfence-reduction pattern) ----
    __threadfence();
    __shared__ unsigned rank;
    if (tid == 0) rank = atomicAdd(&g_cnt[b], 1u);
    __syncthreads();
    if (rank != CHUNKS - 1) return;
    __threadfence();   // ensure all other blocks' g_part/alphat writes are observed

    // Z_b from the 32 chunk Z-slots (warp 0), broadcast via shared
    __shared__ float zsh;
    if (tid < 32) {
        float z = g_part[(b * CHUNKS + tid) * PSTRIDE + H2_];
#pragma unroll
        for (int o = 16; o; o >>= 1) z += __shfl_xor_sync(0xffffffffu, z, o);
        if (tid == 0) zsh = 1.0f / z;
    }
    __syncthreads();
    float iz = zsh;

    // ct_e[b] (fixed chunk order -> deterministic)
    {
        float acc = 0.f;
#pragma unroll
        for (int c = 0; c < CHUNKS; c++)
            acc += g_part[(b * CHUNKS + c) * PSTRIDE + tid];
        ct[b * H2_ + tid] = acc * iz;
    }

    // scale alphat[b, :] in place: 2048 float4 over 256 threads (L2-hot)
    {
        float4* ap = reinterpret_cast<float4*>(alphat_out + (size_t)b * S_);
#pragma unroll
        for (int r = 0; r < 8; r++) {
            int idx = r * 256 + tid;
            float4 v = ap[idx];
            v.x *= iz; v.y *= iz; v.z *= iz; v.w *= iz;
            ap[idx] = v;
        }
    }

    // reset counter for next graph replay
    __threadfence();
    if (tid == 0) atomicExch(&g_cnt[b], 0u);
}

extern "C" void kernel_launch(void* const* d_in, const int* in_sizes, int n_in,
                              void* d_out, int out_size)
{
    const float* h_d_t = (const float*)d_in[0];   // (32,256)
    const float* h_enc = (const float*)d_in[1];   // (32,8192,256)
    const float* mask  = (const float*)d_in[2];   // (32,8192)
    const float* sums  = (const float*)d_in[3];   // (32,8192)
    const float* W     = (const float*)d_in[4];   // (256,256)

    float* out      = (float*)d_out;
    float* ct_e     = out;                        // 32*256
    float* alphat   = out + B_ * H2_;             // 32*8192
    float* newsum   = out + B_ * H2_ + B_ * S_;   // 32*8192

    k_u1<<<B_ * USLICES, 256>>>(h_d_t, W);
    k_main<<<NBLK, 256>>>(h_enc, mask, sums, alphat, newsum, ct_e);
}

// round 12
// speedup vs baseline: 1.0266x; 1.0266x over previous
#include <cuda_runtime.h>
#include <cstddef>

#define B_  32
#define S_  8192
#define H2_ 256
#define CHUNKS 16
#define SPC (S_ / CHUNKS)      // 512 s-rows per block
#define NBLK (B_ * CHUNKS)     // 512 blocks -> single resident wave @ 4 CTA/SM
#define PSTRIDE (H2_ + 1)
#define USLICES 8              // d-dimension slices for k_u1

// ---- scratch (allocation-free) ----
__device__ float g_upart[B_ * USLICES * H2_];       // partial u per d-slice
__device__ float g_part[NBLK * PSTRIDE];            // per-block partial acc[256] + Z
__device__ unsigned g_cnt[B_];                      // arrival counters (self-resetting)

// ---------------- k_u1: partial u[b,e] over a 32-wide d-slice ----------------
__global__ void __launch_bounds__(256) k_u1(const float* __restrict__ hd,
                                            const float* __restrict__ W) {
    int blk = blockIdx.x;            // 256 blocks
    int b = blk >> 3;
    int sl = blk & 7;
    int e = threadIdx.x;
    __shared__ float sh[32];
    if (e < 32) sh[e] = hd[b * H2_ + sl * 32 + e];
    __syncthreads();
    const float* Wp = W + (size_t)(sl * 32) * H2_ + e;
    float acc = 0.f;
#pragma unroll
    for (int d = 0; d < 32; d++) acc += sh[d] * Wp[(size_t)d * H2_];
    g_upart[blk * H2_ + e] = acc;
}

// ---------------- k_main: fused scores + accumulation + per-batch epilogue ----------------
__global__ void __launch_bounds__(256) k_main(
    const float* __restrict__ henc,
    const float* __restrict__ mask,
    const float* __restrict__ sums,
    float* __restrict__ alphat_out,
    float* __restrict__ newsum_out,
    float* __restrict__ ct)
{
    int blk = blockIdx.x;
    int b = blk >> 4;            // / CHUNKS
    int chunk = blk & 15;        // % CHUNKS
    int tid = threadIdx.x;
    int w = tid >> 5;
    int l = tid & 31;

    // u[b] reconstructed from 8 L2-resident d-slice partials.
    // lane l holds dims [4l,4l+4) and [128+4l,128+4l+4)
    float4 u0 = make_float4(0.f, 0.f, 0.f, 0.f);
    float4 u1 = make_float4(0.f, 0.f, 0.f, 0.f);
#pragma unroll
    for (int s2 = 0; s2 < USLICES; s2++) {
        const float4* p = reinterpret_cast<const float4*>(
            g_upart + (size_t)(b * USLICES + s2) * H2_);
        float4 t0 = p[l];
        float4 t1 = p[l + 32];
        u0.x += t0.x; u0.y += t0.y; u0.z += t0.z; u0.w += t0.w;
        u1.x += t1.x; u1.y += t1.y; u1.z += t1.z; u1.w += t1.w;
    }

    float acc0x = 0.f, acc0y = 0.f, acc0z = 0.f, acc0w = 0.f;
    float acc1x = 0.f, acc1y = 0.f, acc1z = 0.f, acc1w = 0.f;
    float Z = 0.f;

    int s0 = chunk * SPC;
    const float4* base = reinterpret_cast<const float4*>(
        henc + ((size_t)b * S_ + s0) * H2_);
    const float* sums_b = sums + b * S_ + s0;
    const float* mask_b = mask + b * S_ + s0;
    float* newsum_b = newsum_out + b * S_ + s0;
    float* alphat_b = alphat_out + b * S_ + s0;

    // 2-row unroll per warp: rows i (A) and i+8 (B) -> MLP=4 LDG.128 per warp
    for (int i = w; i < SPC; i += 16) {
        int j = i + 8;
        const float4* rowA = base + (size_t)i * (H2_ / 4);
        const float4* rowB = base + (size_t)j * (H2_ / 4);
        float4 a0 = __ldcs(rowA + l);
        float4 a1 = __ldcs(rowA + l + 32);
        float4 b0 = __ldcs(rowB + l);
        float4 b1 = __ldcs(rowB + l + 32);

        // issue the scalar side-loads BEFORE the shfl chain so their latency
        // overlaps the reduction instead of extending the critical path
        float seA = 0.f, mA = 0.f, seB = 0.f, mB = 0.f;
        if (l == 0) {
            seA = sums_b[i]; mA = mask_b[i];
            seB = sums_b[j]; mB = mask_b[j];
        }

        float dA = a0.x * u0.x + a0.y * u0.y + a0.z * u0.z + a0.w * u0.w
                 + a1.x * u1.x + a1.y * u1.y + a1.z * u1.z + a1.w * u1.w;
        float dB = b0.x * u0.x + b0.y * u0.y + b0.z * u0.z + b0.w * u0.w
                 + b1.x * u1.x + b1.y * u1.y + b1.z * u1.z + b1.w * u1.w;
#pragma unroll
        for (int o = 16; o; o >>= 1) {      // two independent shfl chains overlap
            dA += __shfl_xor_sync(0xffffffffu, dA, o);
            dB += __shfl_xor_sync(0xffffffffu, dB, o);
        }

        seA = __shfl_sync(0xffffffffu, seA, 0);
        mA  = __shfl_sync(0xffffffffu, mA, 0);
        seB = __shfl_sync(0xffffffffu, seB, 0);
        mB  = __shfl_sync(0xffffffffu, mB, 0);

        float eA = __expf(dA);
        float eB = __expf(dB);
        float aA = (eA / seA) * mA;
        float aB = (eB / seB) * mB;
        if (l == 0) {
            newsum_b[i] = seA + eA;
            alphat_b[i] = aA;            // scaled by invZ in epilogue
            newsum_b[j] = seB + eB;
            alphat_b[j] = aB;
        }
        Z += aA + aB;
        acc0x += aA * a0.x + aB * b0.x;
        acc0y += aA * a0.y + aB * b0.y;
        acc0z += aA * a0.z + aB * b0.z;
        acc0w += aA * a0.w + aB * b0.w;
        acc1x += aA * a1.x + aB * b1.x;
        acc1y += aA * a1.y + aB * b1.y;
        acc1z += aA * a1.z + aB * b1.z;
        acc1w += aA * a1.w + aB * b1.w;
    }

    // block-level reduction of acc[256] across 8 warps (deterministic order)
    __shared__ float sacc[8][H2_];
    __shared__ float sZ[8];
    float* my = sacc[w];
    my[4 * l + 0] = acc0x; my[4 * l + 1] = acc0y;
    my[4 * l + 2] = acc0z; my[4 * l + 3] = acc0w;
    my[128 + 4 * l + 0] = acc1x; my[128 + 4 * l + 1] = acc1y;
    my[128 + 4 * l + 2] = acc1z; my[128 + 4 * l + 3] = acc1w;
    if (l == 0) sZ[w] = Z;
    __syncthreads();

    float tot = 0.f;
#pragma unroll
    for (int ww = 0; ww < 8; ww++) tot += sacc[ww][tid];
    g_part[blk * PSTRIDE + tid] = tot;
    if (tid == 0) {
        float z = 0.f;
#pragma unroll
        for (int ww = 0; ww < 8; ww++) z += sZ[ww];
        g_part[blk * PSTRIDE + H2_] = z;
    }

    // ---- last-block-per-batch epilogue (threadfence-reduction pattern) ----
    __threadfence();
    __shared__ unsigned rank;
    if (tid == 0) rank = atomicAdd(&g_cnt[b], 1u);
    __syncthreads();
    if (rank != CHUNKS - 1) return;
    __threadfence();   // ensure all other blocks' g_part/alphat writes are observed

    // Z_b from the 16 chunk Z-slots (warp 0), broadcast via shared
    __shared__ float zsh;
    if (tid < 32) {
        float z = (l < CHUNKS) ? g_part[(b * CHUNKS + l) * PSTRIDE + H2_] : 0.f;
#pragma unroll
        for (int o = 16; o; o >>= 1) z += __shfl_xor_sync(0xffffffffu, z, o);
        if (tid == 0) zsh = 1.0f / z;
    }
    __syncthreads();
    float iz = zsh;

    // ct_e[b] (fixed chunk order -> deterministic)
    {
        float acc = 0.f;
#pragma unroll
        for (int c = 0; c < CHUNKS; c++)
            acc += g_part[(b * CHUNKS + c) * PSTRIDE + tid];
        ct[b * H2_ + tid] = acc * iz;
    }

    // scale alphat[b, :] in place: 2048 float4 over 256 threads (L2-hot)
    {
        float4* ap = reinterpret_cast<float4*>(alphat_out + (size_t)b * S_);
#pragma unroll
        for (int r = 0; r < 8; r++) {
            int idx = r * 256 + tid;
            float4 v = ap[idx];
            v.x *= iz; v.y *= iz; v.z *= iz; v.w *= iz;
            ap[idx] = v;
        }
    }

    // reset counter for next graph replay
    __threadfence();
    if (tid == 0) atomicExch(&g_cnt[b], 0u);
}

extern "C" void kernel_launch(void* const* d_in, const int* in_sizes, int n_in,
                              void* d_out, int out_size)
{
    const float* h_d_t = (const float*)d_in[0];   // (32,256)
    const float* h_enc = (const float*)d_in[1];   // (32,8192,256)
    const float* mask  = (const float*)d_in[2];   // (32,8192)
    const float* sums  = (const float*)d_in[3];   // (32,8192)
    const float* W     = (const float*)d_in[4];   // (256,256)

    float* out      = (float*)d_out;
    float* ct_e     = out;                        // 32*256
    float* alphat   = out + B_ * H2_;             // 32*8192
    float* newsum   = out + B_ * H2_ + B_ * S_;   // 32*8192

    k_u1<<<B_ * USLICES, 256>>>(h_d_t, W);
    k_main<<<NBLK, 256>>>(h_enc, mask, sums, alphat, newsum, ct_e);
}